// round 6
// baseline (speedup 1.0000x reference)
#include <cuda_runtime.h>
#include <math.h>
#include <stdint.h>

#define DIMC 512
#define HC 8
#define HDC 64
#define BC 2
#define SC 512
#define BHC 16
#define EPSC 1e-5f

// ---------------- scratch (device globals; no allocation allowed) ----------------
__device__ float g_qkv[BC * SC * 3 * DIMC];   // [1024][1536]
__device__ float g_W  [BHC * SC * SC];        // fp32 W
__device__ float g_Wh [BHC * SC * SC];        // tf32 hi/lo of W
__device__ float g_Wl [BHC * SC * SC];
__device__ float g_Zh [BHC * SC * SC];        // tf32 hi/lo of Z = 2I - Yt
__device__ float g_Zl [BHC * SC * SC];
__device__ float g_Xh0[BHC * SC * SC];        // tf32 hi/lo of Xt (double buffered)
__device__ float g_Xl0[BHC * SC * SC];
__device__ float g_Xh1[BHC * SC * SC];
__device__ float g_Xl1[BHC * SC * SC];
__device__ float g_X0 [BHC * SC * SC];        // fp32 Xt (double buffered)
__device__ float g_X1 [BHC * SC * SC];
__device__ float g_xh [BC * SC * DIMC];       // splits of x
__device__ float g_xl [BC * SC * DIMC];
__device__ float g_wqh[3 * DIMC * DIMC];      // splits of qkv_w
__device__ float g_wql[3 * DIMC * DIMC];
__device__ float g_pwh[DIMC * DIMC];          // splits of proj_w
__device__ float g_pwl[DIMC * DIMC];
__device__ float g_gah[BC * SC * DIMC];       // splits of ga
__device__ float g_gal[BC * SC * DIMC];
__device__ float g_ctx [BHC * SC * HDC];
__device__ float g_ctx2[BHC * SC * HDC];
__device__ float g_ga [BC * SC * DIMC];
__device__ float g_scale[BHC];
__device__ float g_mu  [HC * SC];
__device__ float g_rstd[HC * SC];

// ============================ helpers ============================================
__device__ __forceinline__ uint32_t smem_to_u32(const void* p) {
    uint32_t a;
    asm("{ .reg .u64 t; cvta.to.shared.u64 t, %1; cvt.u32.u64 %0, t; }" : "=r"(a) : "l"(p));
    return a;
}
__device__ __forceinline__ void cpa16(uint32_t dst, const float* src) {
    asm volatile("cp.async.cg.shared.global [%0], [%1], 16;" :: "r"(dst), "l"(src));
}
__device__ __forceinline__ void cpa_commit() {
    asm volatile("cp.async.commit_group;" ::: "memory");
}
__device__ __forceinline__ uint2 tf32_split(float v) {
    uint32_t h, l;
    asm("cvt.rna.tf32.f32 %0, %1;" : "=r"(h) : "f"(v));
    float r = v - __uint_as_float(h);
    asm("cvt.rna.tf32.f32 %0, %1;" : "=r"(l) : "f"(r));
    return make_uint2(h, l);
}
__device__ __forceinline__ void mma8(float d[4], const uint32_t a[4],
                                     uint32_t b0, uint32_t b1) {
    asm volatile(
        "mma.sync.aligned.m16n8k8.row.col.f32.tf32.tf32.f32 "
        "{%0,%1,%2,%3}, {%4,%5,%6,%7}, {%8,%9}, {%0,%1,%2,%3};"
        : "+f"(d[0]), "+f"(d[1]), "+f"(d[2]), "+f"(d[3])
        : "r"(a[0]), "r"(a[1]), "r"(a[2]), "r"(a[3]), "r"(b0), "r"(b1));
}

// ---------------- elementwise tf32 split ----------------------------------------
__global__ __launch_bounds__(256) void split_kernel(
    const float* __restrict__ in, float* __restrict__ oh, float* __restrict__ ol)
{
    const int i = blockIdx.x * 256 + threadIdx.x;
    const float4 v = ((const float4*)in)[i];
    const uint2 a = tf32_split(v.x), b = tf32_split(v.y);
    const uint2 c = tf32_split(v.z), d = tf32_split(v.w);
    ((uint4*)oh)[i] = make_uint4(a.x, b.x, c.x, d.x);
    ((uint4*)ol)[i] = make_uint4(a.y, b.y, c.y, d.y);
}

// ================= pre-split 3xTF32 GEMM (mma.sync m16n8k8) ======================
// C = op_A(A) @ op_B(B); operands given as tf32 hi/lo pairs. CTA tile 128x128,
// BK=16 double-buffered cp.async, 256 threads, warp tile 32x64.
// BT=1: B row-major [n][k] (NT); BT=0: B row-major [k][n] (NN).
// Epilogue: v = acc * (SCALE ? g_scale[z] : 1);
//   OF32:  Cf = v + (BIAS ? bias : 0)
//   OSPLIT: z = ZDIAG ? (2I - v) : v; write tf32 split to Ch/Cl.
#define PS_ASTG 2560                 // 128 rows x 20 floats
#define PS_BSTG_NT 2560
#define PS_BSTG_NN 2176              // 16 rows x 136 floats
#define PS_STG(BT)  (2 * PS_ASTG + 2 * ((BT) ? PS_BSTG_NT : PS_BSTG_NN))
#define PS_SMEM(BT) (2 * PS_STG(BT) * 4)

template<int BT>
__device__ __forceinline__ void ps_issue(
    const float* __restrict__ Ah, const float* __restrict__ Al,
    const float* __restrict__ Bh, const float* __restrict__ Bl,
    int lda, int ldb, int m0, int n0, int t, int k0, uint32_t sbase)
{
    const uint32_t aH = sbase;
    const uint32_t aL = sbase + PS_ASTG * 4;
    const uint32_t bH = sbase + 2 * PS_ASTG * 4;
    const uint32_t bL = bH + (BT ? PS_BSTG_NT : PS_BSTG_NN) * 4;
#pragma unroll
    for (int i = 0; i < 2; i++) {
        const int idx = t + i * 256;
        const int r = idx >> 2, c4 = (idx & 3) * 4;
        const long go = (long)(m0 + r) * lda + k0 + c4;
        const uint32_t so = (uint32_t)(r * 20 + c4) * 4u;
        cpa16(aH + so, Ah + go);
        cpa16(aL + so, Al + go);
    }
#pragma unroll
    for (int i = 0; i < 2; i++) {
        const int idx = t + i * 256;
        if (BT) {
            const int r = idx >> 2, c4 = (idx & 3) * 4;
            const long go = (long)(n0 + r) * ldb + k0 + c4;
            const uint32_t so = (uint32_t)(r * 20 + c4) * 4u;
            cpa16(bH + so, Bh + go);
            cpa16(bL + so, Bl + go);
        } else {
            const int kr = idx >> 5, c4 = (idx & 31) * 4;
            const long go = (long)(k0 + kr) * ldb + n0 + c4;
            const uint32_t so = (uint32_t)(kr * 136 + c4) * 4u;
            cpa16(bH + so, Bh + go);
            cpa16(bL + so, Bl + go);
        }
    }
    cpa_commit();
}

template<int BT, int ZDIAG, int SCALE, int BIAS, int OSPLIT, int OF32>
__global__ __launch_bounds__(256, 2) void mma_ps(
    const float* __restrict__ Ah, const float* __restrict__ Al,
    const float* __restrict__ Bh, const float* __restrict__ Bl,
    float* __restrict__ Ch, float* __restrict__ Cl, float* __restrict__ Cf,
    const float* __restrict__ bias,
    int lda, int ldb, int ldc, long aB, long bB, long cB)
{
    extern __shared__ char dsm[];
    const uint32_t sb = smem_to_u32(dsm);
    const int t = threadIdx.x;
    const int w = t >> 5, lane = t & 31;
    const int tg = lane >> 2, tig = lane & 3;
    const int wm = (w & 3) * 32, wn = (w >> 2) * 64;
    const int m0 = blockIdx.y * 128, n0 = blockIdx.x * 128;
    const long zb = blockIdx.z;
    const float* pAh = Ah + zb * aB;
    const float* pAl = Al + zb * aB;
    const float* pBh = Bh + zb * bB;
    const float* pBl = Bl + zb * bB;
    const int stgf = PS_STG(BT);

    float acc[2][8][4];
#pragma unroll
    for (int i = 0; i < 2; i++)
#pragma unroll
        for (int j = 0; j < 8; j++)
#pragma unroll
            for (int p = 0; p < 4; p++) acc[i][j][p] = 0.f;

    ps_issue<BT>(pAh, pAl, pBh, pBl, lda, ldb, m0, n0, t, 0, sb);

    for (int kb = 0; kb < 32; kb++) {
        if (kb < 31) {
            ps_issue<BT>(pAh, pAl, pBh, pBl, lda, ldb, m0, n0, t,
                         (kb + 1) * 16, sb + ((kb + 1) & 1) * stgf * 4);
            asm volatile("cp.async.wait_group 1;" ::: "memory");
        } else {
            asm volatile("cp.async.wait_group 0;" ::: "memory");
        }
        __syncthreads();

        const uint32_t* S = (const uint32_t*)(dsm + (kb & 1) * stgf * 4);
        const uint32_t* AhS = S;
        const uint32_t* AlS = S + PS_ASTG;
        const uint32_t* BhS = S + 2 * PS_ASTG;
        const uint32_t* BlS = BhS + (BT ? PS_BSTG_NT : PS_BSTG_NN);

#pragma unroll
        for (int kk = 0; kk < 2; kk++) {
            const int kc = kk * 8 + tig;
            uint32_t ah[2][4], al[2][4];
#pragma unroll
            for (int mt = 0; mt < 2; mt++) {
                const int ml = wm + 16 * mt + tg;
                ah[mt][0] = AhS[ml * 20 + kc];
                ah[mt][1] = AhS[(ml + 8) * 20 + kc];
                ah[mt][2] = AhS[ml * 20 + kc + 4];
                ah[mt][3] = AhS[(ml + 8) * 20 + kc + 4];
                al[mt][0] = AlS[ml * 20 + kc];
                al[mt][1] = AlS[(ml + 8) * 20 + kc];
                al[mt][2] = AlS[ml * 20 + kc + 4];
                al[mt][3] = AlS[(ml + 8) * 20 + kc + 4];
            }
#pragma unroll
            for (int nt = 0; nt < 8; nt++) {
                const int nl = wn + 8 * nt + tg;
                uint32_t bh0, bh1, bl0, bl1;
                if (BT) {
                    bh0 = BhS[nl * 20 + kc];
                    bh1 = BhS[nl * 20 + kc + 4];
                    bl0 = BlS[nl * 20 + kc];
                    bl1 = BlS[nl * 20 + kc + 4];
                } else {
                    bh0 = BhS[kc * 136 + nl];
                    bh1 = BhS[(kc + 4) * 136 + nl];
                    bl0 = BlS[kc * 136 + nl];
                    bl1 = BlS[(kc + 4) * 136 + nl];
                }
#pragma unroll
                for (int mt = 0; mt < 2; mt++) {
                    mma8(acc[mt][nt], ah[mt], bh0, bh1);   // Ah*Bh
                    mma8(acc[mt][nt], ah[mt], bl0, bl1);   // Ah*Bl
                    mma8(acc[mt][nt], al[mt], bh0, bh1);   // Al*Bh
                }
            }
        }
        __syncthreads();
    }

    // epilogue
    float s = 1.f;
    if (SCALE) s = g_scale[zb];
#pragma unroll
    for (int mt = 0; mt < 2; mt++) {
        const int r0 = m0 + wm + 16 * mt + tg;
#pragma unroll
        for (int nt = 0; nt < 8; nt++) {
            const int c = n0 + wn + 8 * nt + 2 * tig;
            float v0 = acc[mt][nt][0], v1 = acc[mt][nt][1];
            float v2 = acc[mt][nt][2], v3 = acc[mt][nt][3];
            if (SCALE) { v0 *= s; v1 *= s; v2 *= s; v3 *= s; }
            if (OF32) {
                float b0 = 0.f, b1 = 0.f;
                if (BIAS) { b0 = bias[c]; b1 = bias[c + 1]; }
                float* cf = Cf + zb * cB;
                *(float2*)&cf[(long)r0 * ldc + c] = make_float2(v0 + b0, v1 + b1);
                *(float2*)&cf[(long)(r0 + 8) * ldc + c] = make_float2(v2 + b0, v3 + b1);
            }
            if (OSPLIT) {
                if (ZDIAG) {
                    v0 = (r0 == c)     ? 2.f - v0 : -v0;
                    v1 = (r0 == c + 1) ? 2.f - v1 : -v1;
                    v2 = (r0 + 8 == c)     ? 2.f - v2 : -v2;
                    v3 = (r0 + 8 == c + 1) ? 2.f - v3 : -v3;
                }
                const uint2 s0 = tf32_split(v0), s1 = tf32_split(v1);
                const uint2 s2 = tf32_split(v2), s3 = tf32_split(v3);
                uint32_t* ch = (uint32_t*)(Ch + zb * cB);
                uint32_t* cl = (uint32_t*)(Cl + zb * cB);
                *(uint2*)&ch[(long)r0 * ldc + c] = make_uint2(s0.x, s1.x);
                *(uint2*)&cl[(long)r0 * ldc + c] = make_uint2(s0.y, s1.y);
                *(uint2*)&ch[(long)(r0 + 8) * ldc + c] = make_uint2(s2.x, s3.x);
                *(uint2*)&cl[(long)(r0 + 8) * ldc + c] = make_uint2(s2.y, s3.y);
            }
        }
    }
}

// ---------------- small-N SGEMM: 64(M)x64(N) tile, BK=16, 256 threads, 4x4 ------
template<int TRANSA, int ANORM>
__global__ __launch_bounds__(256) void sgemm_n64(
    const float* __restrict__ Ag, const float* __restrict__ Bg, float* __restrict__ Cg,
    int K, int lda, int ldb, int ldc,
    long aO, long aI, long bO, long bI, long cO, long cI)
{
    const int z = blockIdx.z;
    const float* A = Ag + (long)(z >> 3) * aO + (long)(z & 7) * aI;
    const float* B = Bg + (long)(z >> 3) * bO + (long)(z & 7) * bI;
    float*       C = Cg + (long)(z >> 3) * cO + (long)(z & 7) * cI;
    const float* mu   = g_mu   + (z & 7) * SC;
    const float* rstd = g_rstd + (z & 7) * SC;

    const int m0 = blockIdx.x * 64;
    const int t  = threadIdx.x;
    const int ty = t >> 4, tx = t & 15;

    __shared__ float As[16][64];
    __shared__ float Bs[16][64];

    float acc[4][4];
#pragma unroll
    for (int i = 0; i < 4; i++)
#pragma unroll
        for (int j = 0; j < 4; j++) acc[i][j] = 0.f;

    for (int k0 = 0; k0 < K; k0 += 16) {
        if (TRANSA) {
            const int kr = t >> 4, mc = (t & 15) * 4;
            *(float4*)&As[kr][mc] = *(const float4*)&A[(long)(k0 + kr) * lda + m0 + mc];
        } else {
            const int ar = t >> 2, ac = (t & 3) * 4;
            float4 v = *(const float4*)&A[(long)(m0 + ar) * lda + k0 + ac];
            if (ANORM) {
                v.x = (v.x - mu[k0 + ac + 0]) * rstd[k0 + ac + 0];
                v.y = (v.y - mu[k0 + ac + 1]) * rstd[k0 + ac + 1];
                v.z = (v.z - mu[k0 + ac + 2]) * rstd[k0 + ac + 2];
                v.w = (v.w - mu[k0 + ac + 3]) * rstd[k0 + ac + 3];
            }
            As[ac + 0][ar] = v.x;
            As[ac + 1][ar] = v.y;
            As[ac + 2][ar] = v.z;
            As[ac + 3][ar] = v.w;
        }
        {
            const int kr = t >> 4, nc = (t & 15) * 4;
            *(float4*)&Bs[kr][nc] = *(const float4*)&B[(long)(k0 + kr) * ldb + nc];
        }
        __syncthreads();
#pragma unroll
        for (int kk = 0; kk < 16; kk++) {
            float a[4], b[4];
            *(float4*)a = *(const float4*)&As[kk][ty * 4];
            *(float4*)b = *(const float4*)&Bs[kk][tx * 4];
#pragma unroll
            for (int i = 0; i < 4; i++)
#pragma unroll
                for (int j = 0; j < 4; j++)
                    acc[i][j] = fmaf(a[i], b[j], acc[i][j]);
        }
        __syncthreads();
    }

#pragma unroll
    for (int i = 0; i < 4; i++)
#pragma unroll
        for (int j = 0; j < 4; j++)
            C[(long)(m0 + ty * 4 + i) * ldc + tx * 4 + j] = acc[i][j];
}

// ---------------- Laplacian: W[i,j] = tril * exp(-L1/4), plus tf32 split --------
__global__ __launch_bounds__(1024) void laplacian_kernel()
{
    const int z = blockIdx.z;
    const int b = z >> 3, h = z & 7;
    const int i0 = blockIdx.y * 32, j0 = blockIdx.x * 32;
    const int tx = threadIdx.x, ty = threadIdx.y;
    const int tid = ty * 32 + tx;

    float* Wp  = g_W  + (long)z * SC * SC;
    float* Whp = g_Wh + (long)z * SC * SC;
    float* Wlp = g_Wl + (long)z * SC * SC;

    if (j0 > i0 + 31) {
        const long o = (long)(i0 + ty) * SC + j0 + tx;
        Wp[o] = 0.f; Whp[o] = 0.f; Wlp[o] = 0.f;
        return;
    }

    const float* qp = g_qkv + (long)b * SC * 3 * DIMC + h * HDC;
    const float* kp = g_qkv + (long)b * SC * 3 * DIMC + DIMC + h * HDC;

    __shared__ float qs[32][65];
    __shared__ float ks[32][65];

    for (int idx = tid; idx < 2048; idx += 1024) {
        const int r = idx >> 6, d = idx & 63;
        qs[r][d] = qp[(long)(i0 + r) * (3 * DIMC) + d];
        ks[r][d] = kp[(long)(j0 + r) * (3 * DIMC) + d];
    }
    __syncthreads();

    const int i = i0 + ty, j = j0 + tx;
    float out = 0.f;
    if (j <= i) {
        float s = 0.f;
#pragma unroll
        for (int d = 0; d < 64; d++)
            s += fabsf(qs[ty][d] - ks[tx][d]);
        out = expf(-0.25f * s);
    }
    const long o = (long)i * SC + j;
    Wp[o] = out;
    const uint2 sp = tf32_split(out);
    Whp[o] = __uint_as_float(sp.x);
    Wlp[o] = __uint_as_float(sp.y);
}

// ---------------- NS init scale: 1/(max colsum * max rowsum) --------------------
__global__ __launch_bounds__(512) void ns_scale_kernel()
{
    const int z = blockIdx.x;
    const float* W = g_W + (long)z * SC * SC;
    const int t = threadIdx.x;
    const int wid = t >> 5, lid = t & 31;

    float cs = 0.f;
    for (int i = 0; i < SC; i++) cs += W[(long)i * SC + t];

    float rmax = 0.f;
    for (int r = wid; r < SC; r += 16) {
        const float4* row = (const float4*)&W[(long)r * SC];
        float s = 0.f;
#pragma unroll
        for (int p = 0; p < 4; p++) {
            const float4 v = row[lid + p * 32];
            s += v.x + v.y + v.z + v.w;
        }
#pragma unroll
        for (int o = 16; o > 0; o >>= 1) s += __shfl_xor_sync(0xFFFFFFFFu, s, o);
        rmax = fmaxf(rmax, s);
    }

    __shared__ float red[512];
    __shared__ float n1s;
    red[t] = cs; __syncthreads();
    for (int s = 256; s > 0; s >>= 1) {
        if (t < s) red[t] = fmaxf(red[t], red[t + s]);
        __syncthreads();
    }
    if (t == 0) n1s = red[0];
    __syncthreads();
    red[t] = rmax; __syncthreads();
    for (int s = 256; s > 0; s >>= 1) {
        if (t < s) red[t] = fmaxf(red[t], red[t + s]);
        __syncthreads();
    }
    if (t == 0) g_scale[z] = 1.f / (n1s * red[0]);
}

// ---------------- whitening stats per (h, key column j) -------------------------
__global__ __launch_bounds__(256) void stats_kernel()
{
    const int jc = blockIdx.x, h = blockIdx.y;
    const int t = threadIdx.x;
    const int j = jc * 64 + (t & 63);
    const int slice = t >> 6;

    float s = 0.f, s2 = 0.f;
    for (int b = 0; b < BC; b++) {
        const float* Wp = g_W + (long)(b * HC + h) * SC * SC + j;
        for (int i = slice * 128; i < slice * 128 + 128; i++) {
            const float v = Wp[(long)i * SC];
            s += v; s2 += v * v;
        }
    }
    __shared__ float S1[256], S2[256];
    S1[t] = s; S2[t] = s2;
    __syncthreads();
    if (slice == 0) {
        s  = S1[t] + S1[t + 64] + S1[t + 128] + S1[t + 192];
        s2 = S2[t] + S2[t + 64] + S2[t + 128] + S2[t + 192];
        const float n = (float)(BC * SC);
        const float m = s / n;
        const float var = (s2 - n * m * m) / (n - 1.f);
        g_mu[h * SC + j]   = m;
        g_rstd[h * SC + j] = rsqrtf(var + EPSC);
    }
}

// ---------------- launch --------------------------------------------------------
extern "C" void kernel_launch(void* const* d_in, const int* in_sizes, int n_in,
                              void* d_out, int out_size)
{
    (void)in_sizes; (void)n_in; (void)out_size;
    const float* x      = (const float*)d_in[0];
    const float* qkv_w  = (const float*)d_in[1];
    const float* qkv_b  = (const float*)d_in[2];
    const float* proj_w = (const float*)d_in[3];
    const float* proj_b = (const float*)d_in[4];
    float* out = (float*)d_out;

    static float *pQKV = nullptr, *pW, *pWh, *pWl, *pZh, *pZl;
    static float *pXh0, *pXl0, *pXh1, *pXl1, *pX0, *pX1;
    static float *pxh, *pxl, *pwqh, *pwql, *ppwh, *ppwl, *pgah, *pgal;
    static float *pCTX, *pCTX2, *pGA;
    if (!pQKV) {
        cudaGetSymbolAddress((void**)&pQKV, g_qkv);
        cudaGetSymbolAddress((void**)&pW,   g_W);
        cudaGetSymbolAddress((void**)&pWh,  g_Wh);
        cudaGetSymbolAddress((void**)&pWl,  g_Wl);
        cudaGetSymbolAddress((void**)&pZh,  g_Zh);
        cudaGetSymbolAddress((void**)&pZl,  g_Zl);
        cudaGetSymbolAddress((void**)&pXh0, g_Xh0);
        cudaGetSymbolAddress((void**)&pXl0, g_Xl0);
        cudaGetSymbolAddress((void**)&pXh1, g_Xh1);
        cudaGetSymbolAddress((void**)&pXl1, g_Xl1);
        cudaGetSymbolAddress((void**)&pX0,  g_X0);
        cudaGetSymbolAddress((void**)&pX1,  g_X1);
        cudaGetSymbolAddress((void**)&pxh,  g_xh);
        cudaGetSymbolAddress((void**)&pxl,  g_xl);
        cudaGetSymbolAddress((void**)&pwqh, g_wqh);
        cudaGetSymbolAddress((void**)&pwql, g_wql);
        cudaGetSymbolAddress((void**)&ppwh, g_pwh);
        cudaGetSymbolAddress((void**)&ppwl, g_pwl);
        cudaGetSymbolAddress((void**)&pgah, g_gah);
        cudaGetSymbolAddress((void**)&pgal, g_gal);
        cudaGetSymbolAddress((void**)&pCTX, g_ctx);
        cudaGetSymbolAddress((void**)&pCTX2,g_ctx2);
        cudaGetSymbolAddress((void**)&pGA,  g_ga);
        cudaFuncSetAttribute(mma_ps<1,0,0,1,0,1>, cudaFuncAttributeMaxDynamicSharedMemorySize, PS_SMEM(1));
        cudaFuncSetAttribute(mma_ps<1,1,1,0,1,0>, cudaFuncAttributeMaxDynamicSharedMemorySize, PS_SMEM(1));
        cudaFuncSetAttribute(mma_ps<1,1,0,0,1,0>, cudaFuncAttributeMaxDynamicSharedMemorySize, PS_SMEM(1));
        cudaFuncSetAttribute(mma_ps<0,0,1,0,1,1>, cudaFuncAttributeMaxDynamicSharedMemorySize, PS_SMEM(0));
        cudaFuncSetAttribute(mma_ps<0,0,0,0,1,1>, cudaFuncAttributeMaxDynamicSharedMemorySize, PS_SMEM(0));
    }

    const long MS = (long)SC * SC;
    const long CS = (long)SC * HDC;

    // 0) split static operands
    split_kernel<<<512, 256>>>(x, pxh, pxl);           // 1024*512 /1024
    split_kernel<<<768, 256>>>(qkv_w, pwqh, pwql);     // 1536*512 /1024
    split_kernel<<<256, 256>>>(proj_w, ppwh, ppwl);    // 512*512  /1024

    // 1) qkv = x @ qkv_w^T + qkv_b   (NT, fp32 out)
    mma_ps<1,0,0,1,0,1><<<dim3(12, 8, 1), 256, PS_SMEM(1)>>>(
        pxh, pxl, pwqh, pwql, nullptr, nullptr, pQKV, qkv_b, 512, 512, 1536, 0, 0, 0);

    // 2) W = tril(exp(-L1(q,k)/4)) + split
    laplacian_kernel<<<dim3(16, 16, 16), dim3(32, 32)>>>();

    // 3) scale = 1/(n1*ninf)
    ns_scale_kernel<<<16, 512>>>();

    // 5) Newton-Schulz transposed: Z = 2I - Xt@W^T; Xt' = Z@Xt, Xt0 = s*W.
    // it0: Z = 2I - s*(W@W^T);  Xt1 = s*(Z@W)
    mma_ps<1,1,1,0,1,0><<<dim3(4, 4, 16), 256, PS_SMEM(1)>>>(
        pWh, pWl, pWh, pWl, pZh, pZl, nullptr, nullptr, 512, 512, 512, MS, MS, MS);
    mma_ps<0,0,1,0,1,1><<<dim3(4, 4, 16), 256, PS_SMEM(0)>>>(
        pZh, pZl, pWh, pWl, pXh0, pXl0, pX0, nullptr, 512, 512, 512, MS, MS, MS);
    float *curH = pXh0, *curL = pXl0, *curF = pX0;
    float *nxtH = pXh1, *nxtL = pXl1, *nxtF = pX1;
    for (int it = 1; it < 5; it++) {
        mma_ps<1,1,0,0,1,0><<<dim3(4, 4, 16), 256, PS_SMEM(1)>>>(
            curH, curL, pWh, pWl, pZh, pZl, nullptr, nullptr, 512, 512, 512, MS, MS, MS);
        mma_ps<0,0,0,0,1,1><<<dim3(4, 4, 16), 256, PS_SMEM(0)>>>(
            pZh, pZl, curH, curL, nxtH, nxtL, nxtF, nullptr, 512, 512, 512, MS, MS, MS);
        float* t1 = curH; curH = nxtH; nxtH = t1;
        float* t2 = curL; curL = nxtL; nxtL = t2;
        float* t3 = curF; curF = nxtF; nxtF = t3;
    }
    // curF = Xt5 = (W_inv)^T  (fp32)

    // 6) whitening stats
    stats_kernel<<<dim3(8, 8), 256>>>();

    // 7) ctx = W^T @ v
    sgemm_n64<1, 0><<<dim3(8, 1, 16), 256>>>(
        pW, pQKV + 2 * DIMC, pCTX, 512, 512, 3 * DIMC, HDC,
        8 * MS, MS, (long)SC * 3 * DIMC, HDC, 8 * CS, CS);

    // 8) ctx2 = W_inv @ ctx = (Xt5)^T @ ctx
    sgemm_n64<1, 0><<<dim3(8, 1, 16), 256>>>(
        curF, pCTX, pCTX2, 512, 512, HDC, HDC,
        8 * MS, MS, 8 * CS, CS, 8 * CS, CS);

    // 9) ga = W_norm @ ctx2 -> [b, s, h*64+d]
    sgemm_n64<0, 1><<<dim3(8, 1, 16), 256>>>(
        pW, pCTX2, pGA, 512, 512, HDC, 512,
        8 * MS, MS, 8 * CS, CS, MS, HDC);

    // 10) out = ga @ proj_w^T + proj_b   (NT, fp32 out)
    split_kernel<<<512, 256>>>(pGA, pgah, pgal);
    mma_ps<1,0,0,1,0,1><<<dim3(4, 8, 1), 256, PS_SMEM(1)>>>(
        pgah, pgal, ppwh, ppwl, nullptr, nullptr, out, proj_b, 512, 512, 512, 0, 0, 0);
}

// round 7
// speedup vs baseline: 1.6597x; 1.6597x over previous
#include <cuda_runtime.h>
#include <cuda_fp16.h>
#include <math.h>
#include <stdint.h>

#define DIMC 512
#define HC 8
#define HDC 64
#define BC 2
#define SC 512
#define BHC 16
#define EPSC 1e-5f

// ---------------- scratch (device globals; no allocation allowed) ----------------
__device__ float  g_qkv[BC * SC * 3 * DIMC];     // [1024][1536] fp32
__device__ float  g_W  [BHC * SC * SC];          // fp32 W
__device__ __half g_Wh [BHC * SC * SC];          // fp16 hi/lo of W
__device__ __half g_Wl [BHC * SC * SC];
__device__ __half g_Wth[BHC * SC * SC];          // fp16 hi/lo of W^T
__device__ __half g_Wtl[BHC * SC * SC];
__device__ __half g_Zth[BHC * SC * SC];          // fp16 hi/lo of Z^T
__device__ __half g_Ztl[BHC * SC * SC];
__device__ __half g_Xh0[BHC * SC * SC];          // X double buffer (hi/lo)
__device__ __half g_Xl0[BHC * SC * SC];
__device__ __half g_Xh1[BHC * SC * SC];
__device__ __half g_Xl1[BHC * SC * SC];
__device__ __half g_Xth0[BHC * SC * SC];         // X^T double buffer (hi/lo)
__device__ __half g_Xtl0[BHC * SC * SC];
__device__ __half g_Xth1[BHC * SC * SC];
__device__ __half g_Xtl1[BHC * SC * SC];
__device__ float  g_Xf [BHC * SC * SC];          // fp32 X5 = W_inv
__device__ __half g_xh [BC * SC * DIMC];         // splits of x
__device__ __half g_xl [BC * SC * DIMC];
__device__ __half g_wqh[3 * DIMC * DIMC];        // splits of qkv_w
__device__ __half g_wql[3 * DIMC * DIMC];
__device__ __half g_pwh[DIMC * DIMC];            // splits of proj_w
__device__ __half g_pwl[DIMC * DIMC];
__device__ __half g_gah[BC * SC * DIMC];         // splits of ga
__device__ __half g_gal[BC * SC * DIMC];
__device__ float  g_ctx [BHC * SC * HDC];
__device__ float  g_ctx2[BHC * SC * HDC];
__device__ float  g_ga [BC * SC * DIMC];
__device__ float  g_scale[BHC];
__device__ float  g_mu  [HC * SC];
__device__ float  g_rstd[HC * SC];

// ============================ helpers ============================================
__device__ __forceinline__ uint32_t smem_to_u32(const void* p) {
    uint32_t a;
    asm("{ .reg .u64 t; cvta.to.shared.u64 t, %1; cvt.u32.u64 %0, t; }" : "=r"(a) : "l"(p));
    return a;
}
__device__ __forceinline__ void cpa16h(uint32_t dst, const __half* src) {
    asm volatile("cp.async.cg.shared.global [%0], [%1], 16;" :: "r"(dst), "l"(src));
}
__device__ __forceinline__ void cpa_commit() {
    asm volatile("cp.async.commit_group;" ::: "memory");
}
__device__ __forceinline__ void mma16(float d[4], const uint32_t a[4],
                                      uint32_t b0, uint32_t b1) {
    asm volatile(
        "mma.sync.aligned.m16n8k16.row.col.f32.f16.f16.f32 "
        "{%0,%1,%2,%3}, {%4,%5,%6,%7}, {%8,%9}, {%0,%1,%2,%3};"
        : "+f"(d[0]), "+f"(d[1]), "+f"(d[2]), "+f"(d[3])
        : "r"(a[0]), "r"(a[1]), "r"(a[2]), "r"(a[3]), "r"(b0), "r"(b1));
}
__device__ __forceinline__ void h_split(float v, __half& h, __half& l) {
    h = __float2half_rn(v);
    l = __float2half_rn(v - __half2float(h));
}

// ---------------- elementwise fp16 split ----------------------------------------
__global__ __launch_bounds__(256) void split_f16(
    const float* __restrict__ in, __half* __restrict__ oh, __half* __restrict__ ol)
{
    const int i = blockIdx.x * 256 + threadIdx.x;
    const float4 v = ((const float4*)in)[i];
    __half h0, h1, h2, h3, l0, l1, l2, l3;
    h_split(v.x, h0, l0); h_split(v.y, h1, l1);
    h_split(v.z, h2, l2); h_split(v.w, h3, l3);
    ((__half2*)oh)[2 * i]     = __halves2half2(h0, h1);
    ((__half2*)oh)[2 * i + 1] = __halves2half2(h2, h3);
    ((__half2*)ol)[2 * i]     = __halves2half2(l0, l1);
    ((__half2*)ol)[2 * i + 1] = __halves2half2(l2, l3);
}

// ================= 2-term fp16 GEMM (mma.sync m16n8k16), all NT ==================
// C[m][n] = sum_k A[m][k] * B[n][k]   with A = Ah+Al, B = Bh+Bl (3 MMA terms).
// CTA tile 128x128, BK=32 double-buffered cp.async, 128 threads, warp tile 64x64.
// Epilogue: v = acc * (SCALE ? g_scale[z] : 1); if ZDIAG v = 2I - v;
//   OF32: Cf = v + bias;  OH: write h/l split;  OT: write transposed h/l split.
#define MH_ROW 40                    // halves per smem row (32 + pad 8)
#define MH_ARR 5120                  // 128 * 40 halves per array
#define MH_STG_BYTES 40960           // 4 arrays * 10240 B
#define MH_SMEM 81920                // 2 stages

__device__ __forceinline__ void mh_issue(
    const __half* __restrict__ Ah, const __half* __restrict__ Al,
    const __half* __restrict__ Bh, const __half* __restrict__ Bl,
    int lda, int ldb, int m0, int n0, int t, int k0, uint32_t base)
{
#pragma unroll
    for (int i = 0; i < 4; i++) {
        const int idx = t + i * 128;
        const int r = idx >> 2, c8 = (idx & 3) * 8;
        const uint32_t so = (uint32_t)(r * MH_ROW + c8) * 2u;
        cpa16h(base + so,                  Ah + (long)(m0 + r) * lda + k0 + c8);
        cpa16h(base + 10240u + so,         Al + (long)(m0 + r) * lda + k0 + c8);
        cpa16h(base + 20480u + so,         Bh + (long)(n0 + r) * ldb + k0 + c8);
        cpa16h(base + 30720u + so,         Bl + (long)(n0 + r) * ldb + k0 + c8);
    }
    cpa_commit();
}

template<int ZDIAG, int SCALE, int BIAS, int OF32, int OH, int OT>
__global__ __launch_bounds__(128, 2) void mma_h(
    const __half* __restrict__ Ah, const __half* __restrict__ Al,
    const __half* __restrict__ Bh, const __half* __restrict__ Bl,
    __half* __restrict__ Ch, __half* __restrict__ Cl,
    __half* __restrict__ CtH, __half* __restrict__ CtL,
    float* __restrict__ Cf, const float* __restrict__ bias,
    int lda, int ldb, int ldc, long aB, long bB, long cB)
{
    extern __shared__ char dsm[];
    const uint32_t sb = smem_to_u32(dsm);
    const int t = threadIdx.x;
    const int w = t >> 5, lane = t & 31;
    const int tg = lane >> 2, tig = lane & 3;
    const int wm = (w & 1) * 64, wn = (w >> 1) * 64;
    const int m0 = blockIdx.y * 128, n0 = blockIdx.x * 128;
    const long zb = blockIdx.z;
    const __half* pAh = Ah + zb * aB;
    const __half* pAl = Al + zb * aB;
    const __half* pBh = Bh + zb * bB;
    const __half* pBl = Bl + zb * bB;

    float acc[4][8][4];
#pragma unroll
    for (int i = 0; i < 4; i++)
#pragma unroll
        for (int j = 0; j < 8; j++)
#pragma unroll
            for (int p = 0; p < 4; p++) acc[i][j][p] = 0.f;

    mh_issue(pAh, pAl, pBh, pBl, lda, ldb, m0, n0, t, 0, sb);

    for (int kb = 0; kb < 16; kb++) {
        if (kb < 15) {
            mh_issue(pAh, pAl, pBh, pBl, lda, ldb, m0, n0, t,
                     (kb + 1) * 32, sb + ((kb + 1) & 1) * MH_STG_BYTES);
            asm volatile("cp.async.wait_group 1;" ::: "memory");
        } else {
            asm volatile("cp.async.wait_group 0;" ::: "memory");
        }
        __syncthreads();

        const __half* S   = (const __half*)(dsm + (kb & 1) * MH_STG_BYTES);
        const __half* AsH = S;
        const __half* AsL = S + MH_ARR;
        const __half* BsH = S + 2 * MH_ARR;
        const __half* BsL = S + 3 * MH_ARR;

#pragma unroll
        for (int kk = 0; kk < 2; kk++) {
            const int ko = kk * 16 + 2 * tig;
            uint32_t ah[4][4], al[4][4];
#pragma unroll
            for (int mt = 0; mt < 4; mt++) {
                const int rr = (wm + 16 * mt + tg) * MH_ROW + ko;
                ah[mt][0] = *(const uint32_t*)(AsH + rr);
                ah[mt][1] = *(const uint32_t*)(AsH + rr + 8 * MH_ROW);
                ah[mt][2] = *(const uint32_t*)(AsH + rr + 8);
                ah[mt][3] = *(const uint32_t*)(AsH + rr + 8 * MH_ROW + 8);
                al[mt][0] = *(const uint32_t*)(AsL + rr);
                al[mt][1] = *(const uint32_t*)(AsL + rr + 8 * MH_ROW);
                al[mt][2] = *(const uint32_t*)(AsL + rr + 8);
                al[mt][3] = *(const uint32_t*)(AsL + rr + 8 * MH_ROW + 8);
            }
#pragma unroll
            for (int nt = 0; nt < 8; nt++) {
                const int rb = (wn + 8 * nt + tg) * MH_ROW + ko;
                const uint32_t bh0 = *(const uint32_t*)(BsH + rb);
                const uint32_t bh1 = *(const uint32_t*)(BsH + rb + 8);
                const uint32_t bl0 = *(const uint32_t*)(BsL + rb);
                const uint32_t bl1 = *(const uint32_t*)(BsL + rb + 8);
#pragma unroll
                for (int mt = 0; mt < 4; mt++) {
                    mma16(acc[mt][nt], ah[mt], bh0, bh1);   // Ah*Bh
                    mma16(acc[mt][nt], ah[mt], bl0, bl1);   // Ah*Bl
                    mma16(acc[mt][nt], al[mt], bh0, bh1);   // Al*Bh
                }
            }
        }
        __syncthreads();
    }

    // ---------------- epilogue ----------------
    float s = 1.f;
    if (SCALE) s = g_scale[zb];
    __half* tsH = (__half*)dsm;
    __half* tsL = (__half*)(dsm + 34816);

#pragma unroll
    for (int mt = 0; mt < 4; mt++) {
        const int r = wm + 16 * mt + tg;
#pragma unroll
        for (int nt = 0; nt < 8; nt++) {
            const int c = wn + 8 * nt + 2 * tig;
            float v0 = acc[mt][nt][0], v1 = acc[mt][nt][1];
            float v2 = acc[mt][nt][2], v3 = acc[mt][nt][3];
            if (SCALE) { v0 *= s; v1 *= s; v2 *= s; v3 *= s; }
            if (ZDIAG) {
                const int gr = m0 + r, gc = n0 + c;
                v0 = (gr == gc)         ? 2.f - v0 : -v0;
                v1 = (gr == gc + 1)     ? 2.f - v1 : -v1;
                v2 = (gr + 8 == gc)     ? 2.f - v2 : -v2;
                v3 = (gr + 8 == gc + 1) ? 2.f - v3 : -v3;
            }
            if (OF32) {
                float b0 = 0.f, b1 = 0.f;
                if (BIAS) { b0 = bias[n0 + c]; b1 = bias[n0 + c + 1]; }
                float* cf = Cf + zb * cB;
                *(float2*)&cf[(long)(m0 + r) * ldc + n0 + c] = make_float2(v0 + b0, v1 + b1);
                *(float2*)&cf[(long)(m0 + r + 8) * ldc + n0 + c] = make_float2(v2 + b0, v3 + b1);
            }
            if (OH || OT) {
                __half h0, h1, h2, h3, l0, l1, l2, l3;
                h_split(v0, h0, l0); h_split(v1, h1, l1);
                h_split(v2, h2, l2); h_split(v3, h3, l3);
                if (OH) {
                    __half* ch = Ch + zb * cB;
                    __half* cl = Cl + zb * cB;
                    *(__half2*)&ch[(long)(m0 + r) * ldc + n0 + c]     = __halves2half2(h0, h1);
                    *(__half2*)&ch[(long)(m0 + r + 8) * ldc + n0 + c] = __halves2half2(h2, h3);
                    *(__half2*)&cl[(long)(m0 + r) * ldc + n0 + c]     = __halves2half2(l0, l1);
                    *(__half2*)&cl[(long)(m0 + r + 8) * ldc + n0 + c] = __halves2half2(l2, l3);
                }
                if (OT) {
                    tsH[c * 136 + r]           = h0;
                    tsH[(c + 1) * 136 + r]     = h1;
                    tsH[c * 136 + r + 8]       = h2;
                    tsH[(c + 1) * 136 + r + 8] = h3;
                    tsL[c * 136 + r]           = l0;
                    tsL[(c + 1) * 136 + r]     = l1;
                    tsL[c * 136 + r + 8]       = l2;
                    tsL[(c + 1) * 136 + r + 8] = l3;
                }
            }
        }
    }
    if (OT) {
        __syncthreads();
        const uint4* srcH = (const uint4*)(tsH + t * 136);
        const uint4* srcL = (const uint4*)(tsL + t * 136);
        uint4* dH = (uint4*)(CtH + zb * cB + (long)(n0 + t) * ldc + m0);
        uint4* dL = (uint4*)(CtL + zb * cB + (long)(n0 + t) * ldc + m0);
#pragma unroll
        for (int j = 0; j < 16; j++) { dH[j] = srcH[j]; dL[j] = srcL[j]; }
    }
}

// ---------------- small-N SGEMM: 64(M)x64(N) tile, BK=16, 256 threads, 4x4 ------
template<int TRANSA, int ANORM>
__global__ __launch_bounds__(256) void sgemm_n64(
    const float* __restrict__ Ag, const float* __restrict__ Bg, float* __restrict__ Cg,
    int K, int lda, int ldb, int ldc,
    long aO, long aI, long bO, long bI, long cO, long cI)
{
    const int z = blockIdx.z;
    const float* A = Ag + (long)(z >> 3) * aO + (long)(z & 7) * aI;
    const float* B = Bg + (long)(z >> 3) * bO + (long)(z & 7) * bI;
    float*       C = Cg + (long)(z >> 3) * cO + (long)(z & 7) * cI;
    const float* mu   = g_mu   + (z & 7) * SC;
    const float* rstd = g_rstd + (z & 7) * SC;

    const int m0 = blockIdx.x * 64;
    const int t  = threadIdx.x;
    const int ty = t >> 4, tx = t & 15;

    __shared__ float As[16][64];
    __shared__ float Bs[16][64];

    float acc[4][4];
#pragma unroll
    for (int i = 0; i < 4; i++)
#pragma unroll
        for (int j = 0; j < 4; j++) acc[i][j] = 0.f;

    for (int k0 = 0; k0 < K; k0 += 16) {
        if (TRANSA) {
            const int kr = t >> 4, mc = (t & 15) * 4;
            *(float4*)&As[kr][mc] = *(const float4*)&A[(long)(k0 + kr) * lda + m0 + mc];
        } else {
            const int ar = t >> 2, ac = (t & 3) * 4;
            float4 v = *(const float4*)&A[(long)(m0 + ar) * lda + k0 + ac];
            if (ANORM) {
                v.x = (v.x - mu[k0 + ac + 0]) * rstd[k0 + ac + 0];
                v.y = (v.y - mu[k0 + ac + 1]) * rstd[k0 + ac + 1];
                v.z = (v.z - mu[k0 + ac + 2]) * rstd[k0 + ac + 2];
                v.w = (v.w - mu[k0 + ac + 3]) * rstd[k0 + ac + 3];
            }
            As[ac + 0][ar] = v.x;
            As[ac + 1][ar] = v.y;
            As[ac + 2][ar] = v.z;
            As[ac + 3][ar] = v.w;
        }
        {
            const int kr = t >> 4, nc = (t & 15) * 4;
            *(float4*)&Bs[kr][nc] = *(const float4*)&B[(long)(k0 + kr) * ldb + nc];
        }
        __syncthreads();
#pragma unroll
        for (int kk = 0; kk < 16; kk++) {
            float a[4], b[4];
            *(float4*)a = *(const float4*)&As[kk][ty * 4];
            *(float4*)b = *(const float4*)&Bs[kk][tx * 4];
#pragma unroll
            for (int i = 0; i < 4; i++)
#pragma unroll
                for (int j = 0; j < 4; j++)
                    acc[i][j] = fmaf(a[i], b[j], acc[i][j]);
        }
        __syncthreads();
    }

#pragma unroll
    for (int i = 0; i < 4; i++)
#pragma unroll
        for (int j = 0; j < 4; j++)
            C[(long)(m0 + ty * 4 + i) * ldc + tx * 4 + j] = acc[i][j];
}

// ---------------- Laplacian: W = tril(exp(-L1/4)); writes W, Wh/l, Wth/l --------
__global__ __launch_bounds__(1024) void laplacian_kernel()
{
    const int z = blockIdx.z;
    const int b = z >> 3, h = z & 7;
    const int i0 = blockIdx.y * 32, j0 = blockIdx.x * 32;
    const int tx = threadIdx.x, ty = threadIdx.y;
    const int tid = ty * 32 + tx;

    float*  Wp  = g_W   + (long)z * SC * SC;
    __half* Whp = g_Wh  + (long)z * SC * SC;
    __half* Wlp = g_Wl  + (long)z * SC * SC;
    __half* Wth = g_Wth + (long)z * SC * SC;
    __half* Wtl = g_Wtl + (long)z * SC * SC;

    if (j0 > i0 + 31) {   // fully masked tile (uniform per block)
        const long o  = (long)(i0 + ty) * SC + j0 + tx;
        const long ot = (long)(j0 + ty) * SC + i0 + tx;
        Wp[o] = 0.f;
        Whp[o] = __float2half(0.f); Wlp[o] = __float2half(0.f);
        Wth[ot] = __float2half(0.f); Wtl[ot] = __float2half(0.f);
        return;
    }

    const float* qp = g_qkv + (long)b * SC * 3 * DIMC + h * HDC;
    const float* kp = g_qkv + (long)b * SC * 3 * DIMC + DIMC + h * HDC;

    __shared__ float qs[32][65];
    __shared__ float ks[32][65];
    __shared__ float tr[32][33];

    for (int idx = tid; idx < 2048; idx += 1024) {
        const int r = idx >> 6, d = idx & 63;
        qs[r][d] = qp[(long)(i0 + r) * (3 * DIMC) + d];
        ks[r][d] = kp[(long)(j0 + r) * (3 * DIMC) + d];
    }
    __syncthreads();

    const int i = i0 + ty, j = j0 + tx;
    float out = 0.f;
    if (j <= i) {
        float s = 0.f;
#pragma unroll
        for (int d = 0; d < 64; d++)
            s += fabsf(qs[ty][d] - ks[tx][d]);
        out = expf(-0.25f * s);
    }
    const long o = (long)i * SC + j;
    Wp[o] = out;
    __half hh, hl;
    h_split(out, hh, hl);
    Whp[o] = hh; Wlp[o] = hl;

    tr[ty][tx] = out;
    __syncthreads();
    const float tv = tr[tx][ty];              // = W(i0+tx, j0+ty)
    h_split(tv, hh, hl);
    const long ot = (long)(j0 + ty) * SC + i0 + tx;
    Wth[ot] = hh; Wtl[ot] = hl;
}

// ---------------- NS init scale: 1/(max colsum * max rowsum) --------------------
__global__ __launch_bounds__(512) void ns_scale_kernel()
{
    const int z = blockIdx.x;
    const float* W = g_W + (long)z * SC * SC;
    const int t = threadIdx.x;
    const int wid = t >> 5, lid = t & 31;

    float cs = 0.f;
    for (int i = 0; i < SC; i++) cs += W[(long)i * SC + t];

    float rmax = 0.f;
    for (int r = wid; r < SC; r += 16) {
        const float4* row = (const float4*)&W[(long)r * SC];
        float s = 0.f;
#pragma unroll
        for (int p = 0; p < 4; p++) {
            const float4 v = row[lid + p * 32];
            s += v.x + v.y + v.z + v.w;
        }
#pragma unroll
        for (int o = 16; o > 0; o >>= 1) s += __shfl_xor_sync(0xFFFFFFFFu, s, o);
        rmax = fmaxf(rmax, s);
    }

    __shared__ float red[512];
    __shared__ float n1s;
    red[t] = cs; __syncthreads();
    for (int s = 256; s > 0; s >>= 1) {
        if (t < s) red[t] = fmaxf(red[t], red[t + s]);
        __syncthreads();
    }
    if (t == 0) n1s = red[0];
    __syncthreads();
    red[t] = rmax; __syncthreads();
    for (int s = 256; s > 0; s >>= 1) {
        if (t < s) red[t] = fmaxf(red[t], red[t + s]);
        __syncthreads();
    }
    if (t == 0) g_scale[z] = 1.f / (n1s * red[0]);
}

// ---------------- whitening stats per (h, key column j) -------------------------
__global__ __launch_bounds__(256) void stats_kernel()
{
    const int jc = blockIdx.x, h = blockIdx.y;
    const int t = threadIdx.x;
    const int j = jc * 64 + (t & 63);
    const int slice = t >> 6;

    float s = 0.f, s2 = 0.f;
    for (int b = 0; b < BC; b++) {
        const float* Wp = g_W + (long)(b * HC + h) * SC * SC + j;
        for (int i = slice * 128; i < slice * 128 + 128; i++) {
            const float v = Wp[(long)i * SC];
            s += v; s2 += v * v;
        }
    }
    __shared__ float S1[256], S2[256];
    S1[t] = s; S2[t] = s2;
    __syncthreads();
    if (slice == 0) {
        s  = S1[t] + S1[t + 64] + S1[t + 128] + S1[t + 192];
        s2 = S2[t] + S2[t + 64] + S2[t + 128] + S2[t + 192];
        const float n = (float)(BC * SC);
        const float m = s / n;
        const float var = (s2 - n * m * m) / (n - 1.f);
        g_mu[h * SC + j]   = m;
        g_rstd[h * SC + j] = rsqrtf(var + EPSC);
    }
}

// ---------------- launch --------------------------------------------------------
extern "C" void kernel_launch(void* const* d_in, const int* in_sizes, int n_in,
                              void* d_out, int out_size)
{
    (void)in_sizes; (void)n_in; (void)out_size;
    const float* x      = (const float*)d_in[0];
    const float* qkv_w  = (const float*)d_in[1];
    const float* qkv_b  = (const float*)d_in[2];
    const float* proj_w = (const float*)d_in[3];
    const float* proj_b = (const float*)d_in[4];
    float* out = (float*)d_out;

    static float *pQKV = nullptr, *pW, *pXf, *pCTX, *pCTX2, *pGA;
    static __half *pWh, *pWl, *pWth, *pWtl, *pZth, *pZtl;
    static __half *pXh[2], *pXl[2], *pXth[2], *pXtl[2];
    static __half *pxh, *pxl, *pwqh, *pwql, *ppwh, *ppwl, *pgah, *pgal;
    if (!pQKV) {
        cudaGetSymbolAddress((void**)&pQKV, g_qkv);
        cudaGetSymbolAddress((void**)&pW,   g_W);
        cudaGetSymbolAddress((void**)&pWh,  g_Wh);
        cudaGetSymbolAddress((void**)&pWl,  g_Wl);
        cudaGetSymbolAddress((void**)&pWth, g_Wth);
        cudaGetSymbolAddress((void**)&pWtl, g_Wtl);
        cudaGetSymbolAddress((void**)&pZth, g_Zth);
        cudaGetSymbolAddress((void**)&pZtl, g_Ztl);
        cudaGetSymbolAddress((void**)&pXh[0],  g_Xh0);
        cudaGetSymbolAddress((void**)&pXl[0],  g_Xl0);
        cudaGetSymbolAddress((void**)&pXh[1],  g_Xh1);
        cudaGetSymbolAddress((void**)&pXl[1],  g_Xl1);
        cudaGetSymbolAddress((void**)&pXth[0], g_Xth0);
        cudaGetSymbolAddress((void**)&pXtl[0], g_Xtl0);
        cudaGetSymbolAddress((void**)&pXth[1], g_Xth1);
        cudaGetSymbolAddress((void**)&pXtl[1], g_Xtl1);
        cudaGetSymbolAddress((void**)&pXf,  g_Xf);
        cudaGetSymbolAddress((void**)&pxh,  g_xh);
        cudaGetSymbolAddress((void**)&pxl,  g_xl);
        cudaGetSymbolAddress((void**)&pwqh, g_wqh);
        cudaGetSymbolAddress((void**)&pwql, g_wql);
        cudaGetSymbolAddress((void**)&ppwh, g_pwh);
        cudaGetSymbolAddress((void**)&ppwl, g_pwl);
        cudaGetSymbolAddress((void**)&pgah, g_gah);
        cudaGetSymbolAddress((void**)&pgal, g_gal);
        cudaGetSymbolAddress((void**)&pCTX, g_ctx);
        cudaGetSymbolAddress((void**)&pCTX2,g_ctx2);
        cudaGetSymbolAddress((void**)&pGA,  g_ga);
        cudaFuncSetAttribute(mma_h<0,0,1,1,0,0>, cudaFuncAttributeMaxDynamicSharedMemorySize, MH_SMEM);
        cudaFuncSetAttribute(mma_h<1,1,0,0,1,0>, cudaFuncAttributeMaxDynamicSharedMemorySize, MH_SMEM);
        cudaFuncSetAttribute(mma_h<1,0,0,0,1,0>, cudaFuncAttributeMaxDynamicSharedMemorySize, MH_SMEM);
        cudaFuncSetAttribute(mma_h<0,1,0,0,1,1>, cudaFuncAttributeMaxDynamicSharedMemorySize, MH_SMEM);
        cudaFuncSetAttribute(mma_h<0,0,0,0,1,1>, cudaFuncAttributeMaxDynamicSharedMemorySize, MH_SMEM);
        cudaFuncSetAttribute(mma_h<0,0,0,1,0,0>, cudaFuncAttributeMaxDynamicSharedMemorySize, MH_SMEM);
    }

    const long MS = (long)SC * SC;
    const long CS = (long)SC * HDC;

    // 0) split static operands
    split_f16<<<512, 256>>>(x, pxh, pxl);
    split_f16<<<768, 256>>>(qkv_w, pwqh, pwql);
    split_f16<<<256, 256>>>(proj_w, ppwh, ppwl);

    // 1) qkv = x @ qkv_w^T + qkv_b   (NT, fp32 out)
    mma_h<0,0,1,1,0,0><<<dim3(12, 8, 1), 128, MH_SMEM>>>(
        pxh, pxl, pwqh, pwql, nullptr, nullptr, nullptr, nullptr,
        pQKV, qkv_b, 512, 512, 1536, 0, 0, 0);

    // 2) W = tril(exp(-L1/4)) + splits of W and W^T
    laplacian_kernel<<<dim3(16, 16, 16), dim3(32, 32)>>>();

    // 3) scale = 1/(n1*ninf)
    ns_scale_kernel<<<16, 512>>>();

    // 5) Newton-Schulz (dual-orientation, all NT):
    //    Zt = 2I - Xt@W^T ; X' = X@Z (B = Zt) ; Xt' via transposed epilogue.
    //    it0: Xt0 = s*W, X0 = s*Wt (scale applied in epilogue).
    mma_h<1,1,0,0,1,0><<<dim3(4, 4, 16), 128, MH_SMEM>>>(
        pWh, pWl, pWh, pWl, pZth, pZtl, nullptr, nullptr, nullptr, nullptr,
        512, 512, 512, MS, MS, MS);
    mma_h<0,1,0,0,1,1><<<dim3(4, 4, 16), 128, MH_SMEM>>>(
        pWth, pWtl, pZth, pZtl, pXh[0], pXl[0], pXth[0], pXtl[0], nullptr, nullptr,
        512, 512, 512, MS, MS, MS);
    int cur = 0;
    for (int it = 1; it < 4; it++) {
        mma_h<1,0,0,0,1,0><<<dim3(4, 4, 16), 128, MH_SMEM>>>(
            pXth[cur], pXtl[cur], pWh, pWl, pZth, pZtl, nullptr, nullptr, nullptr, nullptr,
            512, 512, 512, MS, MS, MS);
        mma_h<0,0,0,0,1,1><<<dim3(4, 4, 16), 128, MH_SMEM>>>(
            pXh[cur], pXl[cur], pZth, pZtl,
            pXh[1 - cur], pXl[1 - cur], pXth[1 - cur], pXtl[1 - cur], nullptr, nullptr,
            512, 512, 512, MS, MS, MS);
        cur = 1 - cur;
    }
    // it4: final -> fp32 X5 only
    mma_h<1,0,0,0,1,0><<<dim3(4, 4, 16), 128, MH_SMEM>>>(
        pXth[cur], pXtl[cur], pWh, pWl, pZth, pZtl, nullptr, nullptr, nullptr, nullptr,
        512, 512, 512, MS, MS, MS);
    mma_h<0,0,0,1,0,0><<<dim3(4, 4, 16), 128, MH_SMEM>>>(
        pXh[cur], pXl[cur], pZth, pZtl, nullptr, nullptr, nullptr, nullptr,
        pXf, nullptr, 512, 512, 512, MS, MS, MS);

    // 6) whitening stats
    stats_kernel<<<dim3(8, 8), 256>>>();

    // 7) ctx = W^T @ v
    sgemm_n64<1, 0><<<dim3(8, 1, 16), 256>>>(
        pW, pQKV + 2 * DIMC, pCTX, 512, 512, 3 * DIMC, HDC,
        8 * MS, MS, (long)SC * 3 * DIMC, HDC, 8 * CS, CS);

    // 8) ctx2 = W_inv @ ctx  (W_inv = X5, normal orientation)
    sgemm_n64<0, 0><<<dim3(8, 1, 16), 256>>>(
        pXf, pCTX, pCTX2, 512, 512, HDC, HDC,
        8 * MS, MS, 8 * CS, CS, 8 * CS, CS);

    // 9) ga = W_norm @ ctx2 -> [b, s, h*64+d]
    sgemm_n64<0, 1><<<dim3(8, 1, 16), 256>>>(
        pW, pCTX2, pGA, 512, 512, HDC, 512,
        8 * MS, MS, 8 * CS, CS, MS, HDC);

    // 10) out = ga @ proj_w^T + proj_b   (NT, fp32 out)
    split_f16<<<512, 256>>>(pGA, pgah, pgal);
    mma_h<0,0,1,1,0,0><<<dim3(4, 8, 1), 128, MH_SMEM>>>(
        pgah, pgal, ppwh, ppwl, nullptr, nullptr, nullptr, nullptr,
        out, proj_b, 512, 512, 512, 0, 0, 0);
}